// round 4
// baseline (speedup 1.0000x reference)
#include <cuda_runtime.h>
#include <stdint.h>

// Problem constants (fixed shapes per reference)
#define VOCAB   20000
#define TOPK    8
#define GLOVE   300
#define ROW_F   (TOPK * 2 * GLOVE)   // 4800 floats per vocab row
#define OUTC    100
#define B       32
#define L       128
#define NLAB    8
#define NPOS    (B * L)              // 4096
#define NLABTOT (NPOS * NLAB)        // 32768

// Device scratch (no allocations allowed)
__device__ unsigned int g_flags[VOCAB];
__device__ float g_Wt[GLOVE * OUTC];      // W transposed: [300][100]
__device__ float g_P[VOCAB * OUTC];       // 8 MB: per-vocab projected (and /128) 100-vec

#define FMA2(acc, a, w) \
    asm("fma.rn.f32x2 %0, %1, %2, %0;" : "+l"(acc) : "l"(a), "l"(w))
#define DUP2(d, s) \
    asm("mov.b64 %0, {%1, %1};" : "=l"(d) : "f"(s))
#define UNPK2(lo, hi, v) \
    asm("mov.b64 {%0, %1}, %2;" : "=f"(lo), "=f"(hi) : "l"(v))

// ---------------------------------------------------------------------------
// Kernel 1: clear usage flags + transpose W (independent jobs, one launch)
// ---------------------------------------------------------------------------
__global__ void k_init(const float* __restrict__ w) {
    const int i = blockIdx.x * blockDim.x + threadIdx.x;
    if (i < VOCAB) g_flags[i] = 0u;
    if (i < GLOVE * OUTC) {
        const int k = i / OUTC, o = i % OUTC;   // write-coalesced
        g_Wt[i] = w[o * GLOVE + k];
    }
}

// ---------------------------------------------------------------------------
// Kernel 2: mark used vocab entries
// ---------------------------------------------------------------------------
__global__ void k_mark(const int* __restrict__ labels) {
    const int i = blockIdx.x * blockDim.x + threadIdx.x;
    if (i < NLABTOT) g_flags[labels[i]] = 1u;
}

// ---------------------------------------------------------------------------
// Kernel 3: fused row-reduction + projection.
// One block per flagged vocab row.
//  Phase 1 (DRAM-bound): stream 4800 contiguous floats, reduce over the 16
//          rows into smem s[300], prescaled by 1/128.
//  Phase 2 (issue-bound, hides under other blocks' phase-1 DRAM waits):
//          P[v][o] = dot(s, Wt[:,o]) via 8 k-slices x 25 out-quads,
//          FFMA2 + coalesced LDG.128 of L1-resident g_Wt.
// smem ~4.6 KB -> 8 blocks/SM resident.
// ---------------------------------------------------------------------------
__global__ __launch_bounds__(256) void k_rowproj(const float* __restrict__ table) {
    __shared__ float s_sh[GLOVE];
    __shared__ float psum[8 * OUTC];

    const int v = blockIdx.x;
    if (!g_flags[v]) return;
    const float* __restrict__ row = table + (size_t)v * ROW_F;
    const int t = threadIdx.x;
    const float scale = 1.0f / 128.0f;

    // ---- Phase 1: rowsum into smem ----
    {
        float s = 0.0f;
        #pragma unroll
        for (int r = 0; r < 16; ++r) s += row[r * GLOVE + t];
        s_sh[t] = s * scale;
    }
    if (t < GLOVE - 256) {
        const int d = t + 256;
        float s = 0.0f;
        #pragma unroll
        for (int r = 0; r < 16; ++r) s += row[r * GLOVE + d];
        s_sh[d] = s * scale;
    }
    __syncthreads();

    // ---- Phase 2: project 300 -> 100 ----
    if (t < 200) {
        const int q     = t % 25;        // out-quad: outputs 4q..4q+3
        const int slice = t / 25;        // k-slice 0..7
        const int k0 = slice * 38;
        const int k1 = (k0 + 38 < GLOVE) ? (k0 + 38) : GLOVE;

        unsigned long long acc0 = 0ull, acc1 = 0ull;
        const float* wt = g_Wt + 4 * q;
        #pragma unroll 2
        for (int k = k0; k < k1; ++k) {
            const float a = s_sh[k];
            unsigned long long d2; DUP2(d2, a);
            const float4 wv = *reinterpret_cast<const float4*>(wt + k * OUTC);
            unsigned long long w01, w23;
            asm("mov.b64 %0, {%1, %2};" : "=l"(w01) : "f"(wv.x), "f"(wv.y));
            asm("mov.b64 %0, {%1, %2};" : "=l"(w23) : "f"(wv.z), "f"(wv.w));
            FMA2(acc0, d2, w01);
            FMA2(acc1, d2, w23);
        }
        float r0, r1, r2, r3;
        UNPK2(r0, r1, acc0);
        UNPK2(r2, r3, acc1);
        psum[slice * OUTC + 4 * q + 0] = r0;
        psum[slice * OUTC + 4 * q + 1] = r1;
        psum[slice * OUTC + 4 * q + 2] = r2;
        psum[slice * OUTC + 4 * q + 3] = r3;
    }
    __syncthreads();

    // ---- Combine 8 slices, store P[v] ----
    if (t < OUTC) {
        float s = 0.0f;
        #pragma unroll
        for (int sl = 0; sl < 8; ++sl) s += psum[sl * OUTC + t];
        g_P[v * OUTC + t] = s;
    }
}

// ---------------------------------------------------------------------------
// Kernel 4: output gather.  out[pos][o] = sum_8 P[label][o] + bias[o].
// Thread = (pos, out-quad): 4096*25 = 102400 threads. P is 8 MB, L2-resident.
// ---------------------------------------------------------------------------
#define OUT_THREADS 256
#define OUT_TOTAL   (NPOS * 25)

__global__ __launch_bounds__(OUT_THREADS) void k_out(
    const int* __restrict__ labels,
    const float* __restrict__ bias,
    float* __restrict__ out)
{
    const int i = blockIdx.x * OUT_THREADS + threadIdx.x;
    if (i >= OUT_TOTAL) return;
    const int p = i / 25;
    const int q = (i % 25) * 4;

    const int* __restrict__ lab = labels + p * NLAB;
    int l[NLAB];
    #pragma unroll
    for (int j = 0; j < NLAB; ++j) l[j] = lab[j];

    float4 s = *reinterpret_cast<const float4*>(&bias[q]);
    #pragma unroll
    for (int j = 0; j < NLAB; ++j) {
        const float4 v = *reinterpret_cast<const float4*>(&g_P[l[j] * OUTC + q]);
        s.x += v.x; s.y += v.y; s.z += v.z; s.w += v.w;
    }
    *reinterpret_cast<float4*>(&out[p * OUTC + q]) = s;
}

// ---------------------------------------------------------------------------
extern "C" void kernel_launch(void* const* d_in, const int* in_sizes, int n_in,
                              void* d_out, int out_size) {
    const int*   labels = (const int*)  d_in[0];   // [32, 128, 8] int32
    const float* table  = (const float*)d_in[1];   // [20000, 8, 600] f32
    const float* conv_w = (const float*)d_in[2];   // [100, 300]
    const float* conv_b = (const float*)d_in[3];   // [100]
    float*       out    = (float*)d_out;           // [32, 128, 100]

    (void)in_sizes; (void)n_in; (void)out_size;

    k_init<<<(GLOVE * OUTC + 255) / 256, 256>>>(conv_w);
    k_mark<<<(NLABTOT + 255) / 256, 256>>>(labels);
    k_rowproj<<<VOCAB, 256>>>(table);
    k_out<<<(OUT_TOTAL + OUT_THREADS - 1) / OUT_THREADS, OUT_THREADS>>>(labels, conv_b, out);
}